// round 8
// baseline (speedup 1.0000x reference)
#include <cuda_runtime.h>

// Depth-4 path signature, C=10, L=512. Fused kernel, 2 chunks/batch.
// Inner-loop instruction diet: all packed operands come straight from
// shared-memory layout tables (no pack/unpack/splat MOVs in the loop):
//   dxp[t]: 5 u64 pairs (dx[k], dx[k+5])      -> A2 = 1 LDS.64
//   dxd[t]: 10 u64 pairs (dx[k], dx[k])       -> B2,C2 = LDS.64; level-4
//            operands = 5 uniform LDS.128 (broadcast)   [row = 80 bytes]
// Level-4 registers pair ACROSS p: l4q[q] = (L4[p,q], L4[p+500,q]) so the
// packed coef=(clo,chi) feeds FFMA2 directly.
// c=1 writes partial (level4 in paired-u64 layout) + releases flag;
// c=0 keeps partial in regs, spins, merges, writes output.

#define SIG_C 10
#define SIG_L 512
#define SIG_NSTEP 511
#define SIG_OUT 11110
#define SIG_MAXB 128
#define CHUNK0 256

typedef unsigned long long u64;

// partial: [0,110) scalar L1|L2, [110,1110) scalar L3, [1110,11110) paired L4
__device__ __align__(16) float g_part[SIG_MAXB * SIG_OUT];
__device__ int g_flag[SIG_MAXB];   // zero-init; self-resetting

__device__ __forceinline__ u64 ffma2(u64 a, u64 b, u64 c) {
    u64 d; asm("fma.rn.f32x2 %0, %1, %2, %3;" : "=l"(d) : "l"(a), "l"(b), "l"(c)); return d;
}
__device__ __forceinline__ u64 fmul2(u64 a, u64 b) {
    u64 d; asm("mul.rn.f32x2 %0, %1, %2;" : "=l"(d) : "l"(a), "l"(b)); return d;
}
__device__ __forceinline__ u64 fadd2(u64 a, u64 b) {
    u64 d; asm("add.rn.f32x2 %0, %1, %2;" : "=l"(d) : "l"(a), "l"(b)); return d;
}
__device__ __forceinline__ u64 pack2(float lo, float hi) {
    u64 d; asm("mov.b64 %0, {%1, %2};" : "=l"(d) : "f"(lo), "f"(hi)); return d;
}
__device__ __forceinline__ void unpack2(u64 a, float& lo, float& hi) {
    asm("mov.b64 {%0, %1}, %2;" : "=f"(lo), "=f"(hi) : "l"(a));
}

__global__ __launch_bounds__(512, 1)
void sig_fused_kernel(const float* __restrict__ path, float* __restrict__ out) {
    __shared__ __align__(16) float dxd[CHUNK0 * 20];   // (dx[k],dx[k]) x10, 80B/row
    __shared__ __align__(16) float dxp[CHUNK0 * 10];   // (dx[k],dx[k+5]) x5, 40B/row
    __shared__ __align__(16) u64 Bd1[10];
    __shared__ __align__(16) u64 Bd2[100];
    __shared__ __align__(16) u64 Bd3[1000];

    const int b = blockIdx.x >> 1;
    const int c = blockIdx.x & 1;
    const int start = c ? CHUNK0 : 0;
    const int n = c ? (SIG_NSTEP - CHUNK0) : CHUNK0;   // 255 : 256
    const int tid = threadIdx.x;
    const float* prow = path + (size_t)b * SIG_L * SIG_C + (size_t)start * SIG_C;

    for (int i = tid; i < n * SIG_C; i += 512) {
        int t = i / SIG_C;
        int k = i - t * SIG_C;
        float v = prow[(t + 1) * SIG_C + k] - prow[t * SIG_C + k];
        dxd[t * 20 + 2 * k]     = v;
        dxd[t * 20 + 2 * k + 1] = v;
        if (k < 5) dxp[t * 10 + 2 * k]           = v;
        else       dxp[t * 10 + 2 * (k - 5) + 1] = v;
    }
    __syncthreads();

    const bool active = (tid < 500);
    const int i1 = (tid / 100) % 5;
    const int i2 = (tid / 10) % 10;
    const int i3 = tid % 10;

    const u64 c1_2  = pack2(0.5f, 0.5f);
    const u64 c1_6  = pack2(1.0f / 6.0f, 1.0f / 6.0f);
    const u64 c1_24 = pack2(1.0f / 24.0f, 1.0f / 24.0f);

    u64 l1v2 = 0, l2v2 = 0, l3_2 = 0;
    u64 l4q[10];
#pragma unroll
    for (int j = 0; j < 10; ++j) l4q[j] = 0;

    if (active) {
        const u64* dp = reinterpret_cast<const u64*>(dxp) + i1;
        const u64* db = reinterpret_cast<const u64*>(dxd) + i2;
        const u64* dc = reinterpret_cast<const u64*>(dxd) + i3;
        const char* dv = reinterpret_cast<const char*>(dxd);

        // ---- init with exp(dx_0) ----
        {
            u64 A2 = *dp, B2 = *db, C2 = *dc;
            u64 d23_2 = fmul2(B2, C2);
            l1v2 = A2;
            l2v2 = fmul2(fmul2(A2, B2), c1_2);
            l3_2 = fmul2(fmul2(A2, d23_2), c1_6);
            u64 coef = fmul2(l3_2, pack2(0.25f, 0.25f));
            const ulonglong2* vq = reinterpret_cast<const ulonglong2*>(dv);
#pragma unroll
            for (int j = 0; j < 5; ++j) {
                ulonglong2 w = vq[j];
                l4q[2 * j]     = fmul2(coef, w.x);
                l4q[2 * j + 1] = fmul2(coef, w.y);
            }
            dp += 5; db += 10; dc += 10; dv += 80;
        }

        // ---- barrier-free packed scan, no MOVs ----
#pragma unroll 2
        for (int t = 1; t < n; ++t) {
            u64 A2 = *dp, B2 = *db, C2 = *dc;
            ulonglong2 w0 = *reinterpret_cast<const ulonglong2*>(dv);
            ulonglong2 w1 = *reinterpret_cast<const ulonglong2*>(dv + 16);
            ulonglong2 w2 = *reinterpret_cast<const ulonglong2*>(dv + 32);
            ulonglong2 w3 = *reinterpret_cast<const ulonglong2*>(dv + 48);
            ulonglong2 w4 = *reinterpret_cast<const ulonglong2*>(dv + 64);
            dp += 5; db += 10; dc += 10; dv += 80;

            u64 d23_2 = fmul2(B2, C2);
            u64 t1 = fmul2(A2, d23_2);
            u64 uu = fmul2(l2v2, C2);
            u64 vv = fmul2(l1v2, d23_2);
            u64 coef = ffma2(c1_24, t1, ffma2(c1_2, uu, ffma2(c1_6, vv, l3_2)));
            l3_2 = ffma2(c1_6, t1, ffma2(c1_2, vv, fadd2(l3_2, uu)));
            l2v2 = ffma2(ffma2(c1_2, A2, l1v2), B2, l2v2);
            l1v2 = fadd2(l1v2, A2);

            l4q[0] = ffma2(coef, w0.x, l4q[0]);
            l4q[1] = ffma2(coef, w0.y, l4q[1]);
            l4q[2] = ffma2(coef, w1.x, l4q[2]);
            l4q[3] = ffma2(coef, w1.y, l4q[3]);
            l4q[4] = ffma2(coef, w2.x, l4q[4]);
            l4q[5] = ffma2(coef, w2.y, l4q[5]);
            l4q[6] = ffma2(coef, w3.x, l4q[6]);
            l4q[7] = ffma2(coef, w3.y, l4q[7]);
            l4q[8] = ffma2(coef, w4.x, l4q[8]);
            l4q[9] = ffma2(coef, w4.y, l4q[9]);
        }
    }

    float lo, hi;

    if (c == 1) {
        // ---- producer: write partial B, release flag ----
        float* dst = g_part + (size_t)b * SIG_OUT;
        if (active) {
            if (i2 == 0 && i3 == 0) {
                unpack2(l1v2, lo, hi);
                dst[i1] = lo; dst[i1 + 5] = hi;
            }
            if (i3 == 0) {
                unpack2(l2v2, lo, hi);
                dst[10 + i1 * 10 + i2] = lo;
                dst[10 + (i1 + 5) * 10 + i2] = hi;
            }
            unpack2(l3_2, lo, hi);
            dst[110 + tid] = lo;
            dst[110 + tid + 500] = hi;
            u64* d4 = reinterpret_cast<u64*>(dst + 1110) + (size_t)tid * 10;
#pragma unroll
            for (int j = 0; j < 10; ++j) d4[j] = l4q[j];
        }
        __threadfence();
        __syncthreads();
        if (tid == 0) {
            asm volatile("st.release.gpu.global.b32 [%0], %1;"
                         :: "l"(g_flag + b), "r"(1) : "memory");
        }
        return;
    }

    // ---- consumer (chunk 0 = A in registers): spin, merge, write ----
    if (tid == 0) {
        unsigned f;
        do {
            asm volatile("ld.acquire.gpu.global.b32 %0, [%1];"
                         : "=r"(f) : "l"(g_flag + b) : "memory");
        } while (f == 0);
        asm volatile("st.relaxed.gpu.global.b32 [%0], %1;"
                     :: "l"(g_flag + b), "r"(0) : "memory");
    }
    __syncthreads();

    const float* bp = g_part + (size_t)b * SIG_OUT;
    for (int i = tid; i < 1000; i += 512) { float v = bp[110 + i]; Bd3[i] = pack2(v, v); }
    if (tid < 100) { float v = bp[10 + tid]; Bd2[tid] = pack2(v, v); }
    if (tid < 10)  { float v = bp[tid];      Bd1[tid] = pack2(v, v); }
    __syncthreads();

    const float* Bs1 = reinterpret_cast<const float*>(Bd1);
    const float* Bs2 = reinterpret_cast<const float*>(Bd2);
    const float* Bs3 = reinterpret_cast<const float*>(Bd3);
    float* ob = out + (size_t)b * SIG_OUT;

    if (active) {
        // level 4 first (uses old A1,A2,A3 in l1v2,l2v2,l3_2)
        const u64* B4 = reinterpret_cast<const u64*>(bp + 1110) + (size_t)tid * 10;
        const u64* B2r = Bd2 + i3 * 10;
        const u64* B3r = Bd3 + i2 * 100 + i3 * 10;
#pragma unroll
        for (int j = 0; j < 10; ++j) {
            u64 s = fadd2(l4q[j], B4[j]);
            s = ffma2(l3_2, Bd1[j], s);
            s = ffma2(l2v2, B2r[j], s);
            s = ffma2(l1v2, B3r[j], s);
            l4q[j] = s;
        }
        // level 3: A3 + B3 + A2*B1[i3] + A1*B2[i2,i3]
        l3_2 = fadd2(l3_2, pack2(Bs3[2 * tid], Bs3[2 * (tid + 500)]));
        l3_2 = ffma2(l2v2, Bd1[i3], l3_2);
        l3_2 = ffma2(l1v2, Bd2[i2 * 10 + i3], l3_2);
        // level 2: A2 + B2 + A1*B1[i2]
        l2v2 = fadd2(l2v2, pack2(Bs2[2 * (i1 * 10 + i2)], Bs2[2 * ((i1 + 5) * 10 + i2)]));
        l2v2 = ffma2(l1v2, Bd1[i2], l2v2);
        // level 1
        l1v2 = fadd2(l1v2, pack2(Bs1[2 * i1], Bs1[2 * (i1 + 5)]));

        // ---- write output ----
        if (i2 == 0 && i3 == 0) {
            unpack2(l1v2, lo, hi);
            ob[i1] = lo; ob[i1 + 5] = hi;
        }
        if (i3 == 0) {
            unpack2(l2v2, lo, hi);
            ob[10 + i1 * 10 + i2] = lo;
            ob[10 + (i1 + 5) * 10 + i2] = hi;
        }
        unpack2(l3_2, lo, hi);
        ob[110 + tid] = lo;
        ob[110 + tid + 500] = hi;
        float* o4a = ob + 1110 + (size_t)tid * 10;
        float* o4b = ob + 1110 + (size_t)(tid + 500) * 10;
#pragma unroll
        for (int j = 0; j < 10; ++j) {
            unpack2(l4q[j], lo, hi);
            o4a[j] = lo;
            o4b[j] = hi;
        }
    }
}

extern "C" void kernel_launch(void* const* d_in, const int* in_sizes, int n_in,
                              void* d_out, int out_size) {
    const float* path = (const float*)d_in[0];
    float* out = (float*)d_out;
    int B = in_sizes[0] / (SIG_L * SIG_C);
    if (B > SIG_MAXB) B = SIG_MAXB;
    sig_fused_kernel<<<B * 2, 512>>>(path, out);
}

// round 9
// speedup vs baseline: 1.2371x; 1.2371x over previous
#include <cuda_runtime.h>

// Depth-4 path signature, C=10, L=512. One kernel, 2-CTA clusters:
//   cluster = (producer crank0: chunk A = steps [0,256),
//              consumer crank1: chunk B = steps [256,511)).
// Both run the proven R4 register-packed Chen scan. Producer pushes its
// 44KB partial into the consumer's SMEM via mapa + st.shared::cluster
// (DSMEM) -- no global partials, no flags. Cluster barrier, then the
// consumer merges (all LDS) and writes the final signature.

#define SIG_C 10
#define SIG_L 512
#define SIG_NSTEP 511
#define SIG_OUT 11110
#define CHUNK0 256

// dynamic smem layout (bytes)
#define DXS_OFF   0            // float[256*12] = 12288
#define ABUF_OFF  12288        // float[11110]  = 44440
#define BS1_OFF   56728        // float[10]
#define BS2_OFF   56768        // float[100]
#define BS3_OFF   57168        // float[1000]
#define SMEM_BYTES 61168

typedef unsigned long long u64;

__device__ __forceinline__ u64 ffma2(u64 a, u64 b, u64 c) {
    u64 d; asm("fma.rn.f32x2 %0, %1, %2, %3;" : "=l"(d) : "l"(a), "l"(b), "l"(c)); return d;
}
__device__ __forceinline__ u64 fmul2(u64 a, u64 b) {
    u64 d; asm("mul.rn.f32x2 %0, %1, %2;" : "=l"(d) : "l"(a), "l"(b)); return d;
}
__device__ __forceinline__ u64 fadd2(u64 a, u64 b) {
    u64 d; asm("add.rn.f32x2 %0, %1, %2;" : "=l"(d) : "l"(a), "l"(b)); return d;
}
__device__ __forceinline__ u64 pack2(float lo, float hi) {
    u64 d; asm("mov.b64 %0, {%1, %2};" : "=l"(d) : "f"(lo), "f"(hi)); return d;
}
__device__ __forceinline__ void unpack2(u64 a, float& lo, float& hi) {
    asm("mov.b64 {%0, %1}, %2;" : "=f"(lo), "=f"(hi) : "l"(a));
}
__device__ __forceinline__ unsigned smem_u32(const void* p) {
    unsigned a;
    asm("{ .reg .u64 t; cvta.to.shared.u64 t, %1; cvt.u32.u64 %0, t; }" : "=r"(a) : "l"(p));
    return a;
}

__global__ __launch_bounds__(512, 1) __cluster_dims__(2, 1, 1)
void sig_cluster_kernel(const float* __restrict__ path, float* __restrict__ out) {
    extern __shared__ __align__(16) char smem[];
    float* dxs = reinterpret_cast<float*>(smem + DXS_OFF);
    float* Abuf = reinterpret_cast<float*>(smem + ABUF_OFF);
    float* Bs1 = reinterpret_cast<float*>(smem + BS1_OFF);
    float* Bs2 = reinterpret_cast<float*>(smem + BS2_OFF);
    float* Bs3 = reinterpret_cast<float*>(smem + BS3_OFF);

    const int b = blockIdx.x >> 1;
    unsigned crank;
    asm("mov.u32 %0, %%cluster_ctarank;" : "=r"(crank));
    const int start = crank ? CHUNK0 : 0;
    const int n = crank ? (SIG_NSTEP - CHUNK0) : CHUNK0;   // consumer 255 : producer 256
    const int tid = threadIdx.x;
    const float* prow = path + (size_t)b * SIG_L * SIG_C + (size_t)start * SIG_C;

    for (int i = tid; i < n * SIG_C; i += 512) {
        int t = i / SIG_C;
        int cc = i - t * SIG_C;
        dxs[t * 12 + cc] = prow[(t + 1) * SIG_C + cc] - prow[t * SIG_C + cc];
    }
    __syncthreads();

    const bool active = (tid < 500);
    const int i1 = (tid / 100) % 5;
    const int i2 = (tid / 10) % 10;
    const int i3 = tid % 10;

    const u64 c1_2  = pack2(0.5f, 0.5f);
    const u64 c1_6  = pack2(1.0f / 6.0f, 1.0f / 6.0f);
    const u64 c1_24 = pack2(1.0f / 24.0f, 1.0f / 24.0f);

    u64 l1v2 = 0, l2v2 = 0, l3_2 = 0;
    u64 l4lo[5], l4hi[5];
#pragma unroll
    for (int j = 0; j < 5; ++j) { l4lo[j] = 0; l4hi[j] = 0; }

    if (active) {
        // ---- init with exp(dx_0) ----  (verbatim R4)
        {
            float Bv = dxs[i2], Cv = dxs[i3];
            u64 A2 = pack2(dxs[i1], dxs[i1 + 5]);
            float d23 = Bv * Cv;
            u64 d23_2 = pack2(d23, d23);
            u64 B2 = pack2(Bv, Bv);
            l1v2 = A2;
            l2v2 = fmul2(fmul2(A2, B2), c1_2);
            l3_2 = fmul2(fmul2(A2, d23_2), c1_6);
            u64 c4 = fmul2(l3_2, pack2(0.25f, 0.25f));
            float clo, chi; unpack2(c4, clo, chi);
            u64 clo2 = pack2(clo, clo), chi2 = pack2(chi, chi);
            ulonglong2 va = *reinterpret_cast<const ulonglong2*>(dxs);
            ulonglong2 vb = *reinterpret_cast<const ulonglong2*>(dxs + 4);
            u64 vc = *reinterpret_cast<const u64*>(dxs + 8);
            l4lo[0] = fmul2(clo2, va.x); l4hi[0] = fmul2(chi2, va.x);
            l4lo[1] = fmul2(clo2, va.y); l4hi[1] = fmul2(chi2, va.y);
            l4lo[2] = fmul2(clo2, vb.x); l4hi[2] = fmul2(chi2, vb.x);
            l4lo[3] = fmul2(clo2, vb.y); l4hi[3] = fmul2(chi2, vb.y);
            l4lo[4] = fmul2(clo2, vc);   l4hi[4] = fmul2(chi2, vc);
        }

        // ---- barrier-free packed scan ----  (verbatim R4)
        const float* q1 = dxs + i1 + 12;
        const float* q2 = dxs + i2 + 12;
        const float* q3 = dxs + i3 + 12;
        const char*  qv = reinterpret_cast<const char*>(dxs) + 48;

#pragma unroll 4
        for (int t = 1; t < n; ++t) {
            float A_lo = *q1;
            float A_hi = q1[5];
            float Bv = *q2;
            float Cv = *q3;
            ulonglong2 va = *reinterpret_cast<const ulonglong2*>(qv);
            ulonglong2 vb = *reinterpret_cast<const ulonglong2*>(qv + 16);
            u64 vc = *reinterpret_cast<const u64*>(qv + 32);
            q1 += 12; q2 += 12; q3 += 12; qv += 48;

            float d23 = Bv * Cv;
            u64 A2 = pack2(A_lo, A_hi);
            u64 d23_2 = pack2(d23, d23);
            u64 C2 = pack2(Cv, Cv);
            u64 B2 = pack2(Bv, Bv);
            u64 t1 = fmul2(A2, d23_2);
            u64 uu = fmul2(l2v2, C2);
            u64 vv = fmul2(l1v2, d23_2);
            u64 coef = ffma2(c1_24, t1, ffma2(c1_2, uu, ffma2(c1_6, vv, l3_2)));
            l3_2 = ffma2(c1_6, t1, ffma2(c1_2, vv, fadd2(l3_2, uu)));
            l2v2 = ffma2(ffma2(c1_2, A2, l1v2), B2, l2v2);
            l1v2 = fadd2(l1v2, A2);

            float clo, chi; unpack2(coef, clo, chi);
            u64 clo2 = pack2(clo, clo), chi2 = pack2(chi, chi);
            l4lo[0] = ffma2(clo2, va.x, l4lo[0]); l4hi[0] = ffma2(chi2, va.x, l4hi[0]);
            l4lo[1] = ffma2(clo2, va.y, l4lo[1]); l4hi[1] = ffma2(chi2, va.y, l4hi[1]);
            l4lo[2] = ffma2(clo2, vb.x, l4lo[2]); l4hi[2] = ffma2(chi2, vb.x, l4hi[2]);
            l4lo[3] = ffma2(clo2, vb.y, l4lo[3]); l4hi[3] = ffma2(chi2, vb.y, l4hi[3]);
            l4lo[4] = ffma2(clo2, vc,   l4lo[4]); l4hi[4] = ffma2(chi2, vc,   l4hi[4]);
        }
    }

    float lo, hi;

    if (crank == 0) {
        // ---- producer: push partial A into consumer's SMEM via DSMEM ----
        unsigned lbase = smem_u32(smem) + ABUF_OFF;
        unsigned rbase;
        asm("mapa.shared::cluster.u32 %0, %1, %2;" : "=r"(rbase) : "r"(lbase), "r"(1));
        if (active) {
            if (i2 == 0 && i3 == 0) {
                unpack2(l1v2, lo, hi);
                asm volatile("st.shared::cluster.f32 [%0], %1;" :: "r"(rbase + 4u * i1), "f"(lo) : "memory");
                asm volatile("st.shared::cluster.f32 [%0], %1;" :: "r"(rbase + 4u * (i1 + 5)), "f"(hi) : "memory");
            }
            if (i3 == 0) {
                unpack2(l2v2, lo, hi);
                asm volatile("st.shared::cluster.f32 [%0], %1;" :: "r"(rbase + 4u * (10 + i1 * 10 + i2)), "f"(lo) : "memory");
                asm volatile("st.shared::cluster.f32 [%0], %1;" :: "r"(rbase + 4u * (10 + (i1 + 5) * 10 + i2)), "f"(hi) : "memory");
            }
            unpack2(l3_2, lo, hi);
            asm volatile("st.shared::cluster.f32 [%0], %1;" :: "r"(rbase + 4u * (110 + tid)), "f"(lo) : "memory");
            asm volatile("st.shared::cluster.f32 [%0], %1;" :: "r"(rbase + 4u * (110 + tid + 500)), "f"(hi) : "memory");
            unsigned r4lo = rbase + 4u * (1110 + tid * 10);
            unsigned r4hi = rbase + 4u * (1110 + (tid + 500) * 10);
#pragma unroll
            for (int j = 0; j < 5; ++j) {
                asm volatile("st.shared::cluster.u64 [%0], %1;" :: "r"(r4lo + 8u * j), "l"(l4lo[j]) : "memory");
                asm volatile("st.shared::cluster.u64 [%0], %1;" :: "r"(r4hi + 8u * j), "l"(l4hi[j]) : "memory");
            }
        }
        asm volatile("fence.acq_rel.cluster;" ::: "memory");
        asm volatile("barrier.cluster.arrive.aligned;" ::: "memory");
        asm volatile("barrier.cluster.wait.aligned;" ::: "memory");
        return;
    }

    // ---- consumer: stash B levels 1-3 in own smem ----
    if (active) {
        if (i2 == 0 && i3 == 0) {
            unpack2(l1v2, lo, hi);
            Bs1[i1] = lo; Bs1[i1 + 5] = hi;
        }
        if (i3 == 0) {
            unpack2(l2v2, lo, hi);
            Bs2[i1 * 10 + i2] = lo;
            Bs2[(i1 + 5) * 10 + i2] = hi;
        }
        unpack2(l3_2, lo, hi);
        Bs3[tid] = lo;
        Bs3[tid + 500] = hi;
    }
    __syncthreads();
    asm volatile("barrier.cluster.arrive.aligned;" ::: "memory");
    asm volatile("barrier.cluster.wait.aligned;" ::: "memory");

    // ---- merge A (smem, from producer) (x) B (regs/smem), write output ----
    float* ob = out + (size_t)b * SIG_OUT;
    if (active) {
        float a1lo = Abuf[i1], a1hi = Abuf[i1 + 5];
        float a2lo = Abuf[10 + i1 * 10 + i2], a2hi = Abuf[10 + (i1 + 5) * 10 + i2];
        float a3lo = Abuf[110 + tid], a3hi = Abuf[110 + tid + 500];

        // level 1
        if (i2 == 0 && i3 == 0) {
            unpack2(l1v2, lo, hi);
            ob[i1] = a1lo + lo;
            ob[i1 + 5] = a1hi + hi;
        }
        // level 2: A2 + A1[i1]*B1[i2] + B2
        if (i3 == 0) {
            unpack2(l2v2, lo, hi);
            float b1 = Bs1[i2];
            ob[10 + i1 * 10 + i2] = fmaf(a1lo, b1, a2lo + lo);
            ob[10 + (i1 + 5) * 10 + i2] = fmaf(a1hi, b1, a2hi + hi);
        }
        // level 3: A3 + A2*B1[i3] + A1*B2[i2,i3] + B3
        {
            float b1s = Bs1[i3];
            float b2s = Bs2[i2 * 10 + i3];
            u64 l3o = fadd2(pack2(a3lo, a3hi), l3_2);
            l3o = ffma2(pack2(a2lo, a2hi), pack2(b1s, b1s), l3o);
            l3o = ffma2(pack2(a1lo, a1hi), pack2(b2s, b2s), l3o);
            unpack2(l3o, lo, hi);
            ob[110 + tid] = lo;
            ob[110 + tid + 500] = hi;
        }
        // level 4: A4 + A3*B1[q] + A2*B2[i3,q] + A1*B3[i2,i3,q] + B4
        const u64* A4lo = reinterpret_cast<const u64*>(Abuf + 1110 + (size_t)tid * 10);
        const u64* A4hi = reinterpret_cast<const u64*>(Abuf + 1110 + (size_t)(tid + 500) * 10);
        const u64* B1q = reinterpret_cast<const u64*>(Bs1);
        const u64* B2q = reinterpret_cast<const u64*>(Bs2 + i3 * 10);
        const u64* B3q = reinterpret_cast<const u64*>(Bs3 + (i2 * 10 + i3) * 10);
        u64 a3lo2 = pack2(a3lo, a3lo), a3hi2 = pack2(a3hi, a3hi);
        u64 a2lo2 = pack2(a2lo, a2lo), a2hi2 = pack2(a2hi, a2hi);
        u64 a1lo2 = pack2(a1lo, a1lo), a1hi2 = pack2(a1hi, a1hi);
        u64* o4lo = reinterpret_cast<u64*>(ob + 1110 + (size_t)tid * 10);
        u64* o4hi = reinterpret_cast<u64*>(ob + 1110 + (size_t)(tid + 500) * 10);
#pragma unroll
        for (int j = 0; j < 5; ++j) {
            u64 s = fadd2(l4lo[j], A4lo[j]);
            s = ffma2(a3lo2, B1q[j], s);
            s = ffma2(a2lo2, B2q[j], s);
            s = ffma2(a1lo2, B3q[j], s);
            o4lo[j] = s;
            u64 t2 = fadd2(l4hi[j], A4hi[j]);
            t2 = ffma2(a3hi2, B1q[j], t2);
            t2 = ffma2(a2hi2, B2q[j], t2);
            t2 = ffma2(a1hi2, B3q[j], t2);
            o4hi[j] = t2;
        }
    }
}

extern "C" void kernel_launch(void* const* d_in, const int* in_sizes, int n_in,
                              void* d_out, int out_size) {
    const float* path = (const float*)d_in[0];
    float* out = (float*)d_out;
    int B = in_sizes[0] / (SIG_L * SIG_C);
    cudaFuncSetAttribute(sig_cluster_kernel,
                         cudaFuncAttributeMaxDynamicSharedMemorySize, SMEM_BYTES);
    sig_cluster_kernel<<<B * 2, 512, SMEM_BYTES>>>(path, out);
}

// round 10
// speedup vs baseline: 1.3622x; 1.1012x over previous
#include <cuda_runtime.h>

// Depth-4 path signature, C=10, L=512. Two kernels (R4 structure, both
// independently measured) with a memory-friendly combine:
//  - partials store level-4 TRANSPOSED: u64(q-pair j, row p) at j*1000+p
//    -> coalesced stores in scan, coalesced loads in combine.
//  - combine: 64 CTAs x 1024 thr, 1 row/thread, MLP>=10, smem-staged output.

#define SIG_C 10
#define SIG_L 512
#define SIG_NSTEP 511
#define SIG_OUT 11110
#define SIG_MAXB 128
#define CHUNK0 256

typedef unsigned long long u64;

// per chunk partial: [0,110) L1|L2, [110,1110) L3, [1110,11110) L4 transposed
__device__ __align__(16) float g_part[SIG_MAXB * 2 * SIG_OUT];

__device__ __forceinline__ u64 ffma2(u64 a, u64 b, u64 c) {
    u64 d; asm("fma.rn.f32x2 %0, %1, %2, %3;" : "=l"(d) : "l"(a), "l"(b), "l"(c)); return d;
}
__device__ __forceinline__ u64 fmul2(u64 a, u64 b) {
    u64 d; asm("mul.rn.f32x2 %0, %1, %2;" : "=l"(d) : "l"(a), "l"(b)); return d;
}
__device__ __forceinline__ u64 fadd2(u64 a, u64 b) {
    u64 d; asm("add.rn.f32x2 %0, %1, %2;" : "=l"(d) : "l"(a), "l"(b)); return d;
}
__device__ __forceinline__ u64 pack2(float lo, float hi) {
    u64 d; asm("mov.b64 %0, {%1, %2};" : "=l"(d) : "f"(lo), "f"(hi)); return d;
}
__device__ __forceinline__ void unpack2(u64 a, float& lo, float& hi) {
    asm("mov.b64 {%0, %1}, %2;" : "=f"(lo), "=f"(hi) : "l"(a));
}

// ---------------- Kernel 1: per-chunk signature scan (R4 loop verbatim) ----
__global__ __launch_bounds__(512, 1)
void sig_scan_kernel(const float* __restrict__ path) {
    __shared__ __align__(16) float dxs[CHUNK0 * 12];

    const int b = blockIdx.x >> 1;
    const int c = blockIdx.x & 1;
    const int start = c ? CHUNK0 : 0;
    const int n = c ? (SIG_NSTEP - CHUNK0) : CHUNK0;   // 255 : 256
    const int tid = threadIdx.x;
    const float* prow = path + (size_t)b * SIG_L * SIG_C + (size_t)start * SIG_C;

    for (int i = tid; i < n * SIG_C; i += 512) {
        int t = i / SIG_C;
        int cc = i - t * SIG_C;
        dxs[t * 12 + cc] = prow[(t + 1) * SIG_C + cc] - prow[t * SIG_C + cc];
    }
    __syncthreads();

    if (tid >= 500) return;
    const int i1 = tid / 100;          // 0..4 ; hi chain uses i1+5
    const int i2 = (tid / 10) % 10;
    const int i3 = tid % 10;

    const u64 c1_2  = pack2(0.5f, 0.5f);
    const u64 c1_6  = pack2(1.0f / 6.0f, 1.0f / 6.0f);
    const u64 c1_24 = pack2(1.0f / 24.0f, 1.0f / 24.0f);

    u64 l1v2, l2v2, l3_2;
    u64 l4lo[5], l4hi[5];
    {
        float Bv = dxs[i2], Cv = dxs[i3];
        u64 A2 = pack2(dxs[i1], dxs[i1 + 5]);
        float d23 = Bv * Cv;
        u64 d23_2 = pack2(d23, d23);
        u64 B2 = pack2(Bv, Bv);
        l1v2 = A2;
        l2v2 = fmul2(fmul2(A2, B2), c1_2);
        l3_2 = fmul2(fmul2(A2, d23_2), c1_6);
        u64 c4 = fmul2(l3_2, pack2(0.25f, 0.25f));
        float clo, chi; unpack2(c4, clo, chi);
        u64 clo2 = pack2(clo, clo), chi2 = pack2(chi, chi);
        ulonglong2 va = *reinterpret_cast<const ulonglong2*>(dxs);
        ulonglong2 vb = *reinterpret_cast<const ulonglong2*>(dxs + 4);
        u64 vc = *reinterpret_cast<const u64*>(dxs + 8);
        l4lo[0] = fmul2(clo2, va.x); l4hi[0] = fmul2(chi2, va.x);
        l4lo[1] = fmul2(clo2, va.y); l4hi[1] = fmul2(chi2, va.y);
        l4lo[2] = fmul2(clo2, vb.x); l4hi[2] = fmul2(chi2, vb.x);
        l4lo[3] = fmul2(clo2, vb.y); l4hi[3] = fmul2(chi2, vb.y);
        l4lo[4] = fmul2(clo2, vc);   l4hi[4] = fmul2(chi2, vc);
    }

    const float* q1 = dxs + i1 + 12;
    const float* q2 = dxs + i2 + 12;
    const float* q3 = dxs + i3 + 12;
    const char*  qv = reinterpret_cast<const char*>(dxs) + 48;

#pragma unroll 4
    for (int t = 1; t < n; ++t) {
        float A_lo = *q1;
        float A_hi = q1[5];
        float Bv = *q2;
        float Cv = *q3;
        ulonglong2 va = *reinterpret_cast<const ulonglong2*>(qv);
        ulonglong2 vb = *reinterpret_cast<const ulonglong2*>(qv + 16);
        u64 vc = *reinterpret_cast<const u64*>(qv + 32);
        q1 += 12; q2 += 12; q3 += 12; qv += 48;

        float d23 = Bv * Cv;
        u64 A2 = pack2(A_lo, A_hi);
        u64 d23_2 = pack2(d23, d23);
        u64 C2 = pack2(Cv, Cv);
        u64 B2 = pack2(Bv, Bv);
        u64 t1 = fmul2(A2, d23_2);
        u64 uu = fmul2(l2v2, C2);
        u64 vv = fmul2(l1v2, d23_2);
        u64 coef = ffma2(c1_24, t1, ffma2(c1_2, uu, ffma2(c1_6, vv, l3_2)));
        l3_2 = ffma2(c1_6, t1, ffma2(c1_2, vv, fadd2(l3_2, uu)));
        l2v2 = ffma2(ffma2(c1_2, A2, l1v2), B2, l2v2);
        l1v2 = fadd2(l1v2, A2);

        float clo, chi; unpack2(coef, clo, chi);
        u64 clo2 = pack2(clo, clo), chi2 = pack2(chi, chi);
        l4lo[0] = ffma2(clo2, va.x, l4lo[0]); l4hi[0] = ffma2(chi2, va.x, l4hi[0]);
        l4lo[1] = ffma2(clo2, va.y, l4lo[1]); l4hi[1] = ffma2(chi2, va.y, l4hi[1]);
        l4lo[2] = ffma2(clo2, vb.x, l4lo[2]); l4hi[2] = ffma2(chi2, vb.x, l4hi[2]);
        l4lo[3] = ffma2(clo2, vb.y, l4lo[3]); l4hi[3] = ffma2(chi2, vb.y, l4hi[3]);
        l4lo[4] = ffma2(clo2, vc,   l4lo[4]); l4hi[4] = ffma2(chi2, vc,   l4hi[4]);
    }

    // ---- write partial: L1/L2/L3 scalar, L4 transposed-coalesced ----
    float* dst = g_part + ((size_t)b * 2 + c) * SIG_OUT;
    float lo, hi;
    if (i2 == 0 && i3 == 0) {
        unpack2(l1v2, lo, hi);
        dst[i1] = lo; dst[i1 + 5] = hi;
    }
    if (i3 == 0) {
        unpack2(l2v2, lo, hi);
        dst[10 + i1 * 10 + i2] = lo;
        dst[10 + (i1 + 5) * 10 + i2] = hi;
    }
    unpack2(l3_2, lo, hi);
    dst[110 + tid] = lo;
    dst[110 + tid + 500] = hi;
    u64* d4 = reinterpret_cast<u64*>(dst + 1110);
#pragma unroll
    for (int j = 0; j < 5; ++j) {
        d4[j * 1000 + tid]       = l4lo[j];   // rows p=tid, q-pair j
        d4[j * 1000 + tid + 500] = l4hi[j];   // rows p=tid+500
    }
}

// ---------------- Kernel 2: Chen combine, 1 CTA/batch, coalesced -----------
__global__ __launch_bounds__(1024, 1)
void sig_combine_kernel(float* __restrict__ out) {
    __shared__ __align__(16) float As1[10], As2[100];
    __shared__ __align__(16) float Bs1d[16];      // u64-aligned B1 pairs
    __shared__ __align__(16) float Bs2[100];
    __shared__ __align__(16) float Bs3[1000];
    __shared__ __align__(16) float stage[SIG_OUT + 2];

    const int b = blockIdx.x;
    const int tid = threadIdx.x;
    const float* a  = g_part + (size_t)(2 * b) * SIG_OUT;       // chunk A (first)
    const float* bb = g_part + (size_t)(2 * b + 1) * SIG_OUT;   // chunk B (second)

    if (tid < 1000) Bs3[tid] = bb[110 + tid];
    if (tid >= 1000 && tid < 1010) { int k = tid - 1000; As1[k] = a[k]; Bs1d[k] = bb[k]; }
    else if (tid >= 1010 && tid < 1016) Bs1d[tid - 1010 + 10] = 0.0f;
    if (tid < 100) { As2[tid] = a[10 + tid]; Bs2[tid] = bb[10 + tid]; }
    __syncthreads();

    if (tid < 1000) {
        const int p = tid;
        const int i1 = p / 100;
        const int i2 = (p / 10) % 10;
        const int i3 = p % 10;

        // issue all independent global loads up front (coalesced u64)
        const u64* A4 = reinterpret_cast<const u64*>(a + 1110);
        const u64* B4 = reinterpret_cast<const u64*>(bb + 1110);
        u64 a4[5], b4[5];
#pragma unroll
        for (int j = 0; j < 5; ++j) a4[j] = A4[j * 1000 + p];
#pragma unroll
        for (int j = 0; j < 5; ++j) b4[j] = B4[j * 1000 + p];
        float a3 = a[110 + p];
        float b3 = Bs3[p];

        float a1 = As1[i1];
        float a2 = As2[i1 * 10 + i2];

        // level 3
        stage[110 + p] = a3 + b3 + a2 * Bs1d[i3] + a1 * Bs2[i2 * 10 + i3];

        // level 4 (packed over q-pairs)
        const u64* B1q = reinterpret_cast<const u64*>(Bs1d);
        const u64* B2q = reinterpret_cast<const u64*>(Bs2 + i3 * 10);
        const u64* B3q = reinterpret_cast<const u64*>(Bs3 + i2 * 100 + i3 * 10);
        u64 a1_2 = pack2(a1, a1);
        u64 a2_2 = pack2(a2, a2);
        u64 a3_2 = pack2(a3, a3);
        u64* s4 = reinterpret_cast<u64*>(stage + 1110) + (size_t)p * 5;
#pragma unroll
        for (int j = 0; j < 5; ++j) {
            u64 s = fadd2(a4[j], b4[j]);
            s = ffma2(a3_2, B1q[j], s);
            s = ffma2(a2_2, B2q[j], s);
            s = ffma2(a1_2, B3q[j], s);
            s4[j] = s;
        }
    } else if (tid >= 1000 && tid < 1010) {
        int k = tid - 1000;
        stage[k] = As1[k] + Bs1d[k];
    }
    // level 2 by threads 0..99 of the upper range is fine too; reuse tid<100 after sync?
    // do it here with dedicated threads 900..999? They are busy (tid<1000 path).
    __syncthreads();
    if (tid < 100) {
        stage[10 + tid] = As2[tid] + Bs2[tid] + As1[tid / 10] * Bs1d[tid % 10];
    }
    __syncthreads();

    // coalesced copy stage -> out (u64; 44440 bytes % 8 == 0)
    const u64* sp = reinterpret_cast<const u64*>(stage);
    u64* op = reinterpret_cast<u64*>(out + (size_t)b * SIG_OUT);
#pragma unroll
    for (int i = tid; i < SIG_OUT / 2; i += 1024) op[i] = sp[i];
}

extern "C" void kernel_launch(void* const* d_in, const int* in_sizes, int n_in,
                              void* d_out, int out_size) {
    const float* path = (const float*)d_in[0];
    float* out = (float*)d_out;
    int B = in_sizes[0] / (SIG_L * SIG_C);
    if (B > SIG_MAXB) B = SIG_MAXB;
    sig_scan_kernel<<<B * 2, 512>>>(path);
    sig_combine_kernel<<<B, 1024>>>(out);
}

// round 12
// speedup vs baseline: 1.3634x; 1.0009x over previous
#include <cuda_runtime.h>

// Depth-4 path signature, C=10, L=512. Two kernels:
//  K1 scan (VERBATIM R10): 2 chunks/batch, register-packed f32x2 Chen scan,
//     level-4 partials stored TRANSPOSED (u64 at j*1000+p) -> coalesced.
//  K2 combine: 2 CTAs per batch (p-halves), 128 CTAs total, coalesced u64
//     loads, smem-staged contiguous output slices, coalesced u64 stores.

#define SIG_C 10
#define SIG_L 512
#define SIG_NSTEP 511
#define SIG_OUT 11110
#define SIG_MAXB 128
#define CHUNK0 256

typedef unsigned long long u64;

// per chunk partial: [0,110) L1|L2, [110,1110) L3, [1110,11110) L4 transposed
__device__ __align__(16) float g_part[SIG_MAXB * 2 * SIG_OUT];

__device__ __forceinline__ u64 ffma2(u64 a, u64 b, u64 c) {
    u64 d; asm("fma.rn.f32x2 %0, %1, %2, %3;" : "=l"(d) : "l"(a), "l"(b), "l"(c)); return d;
}
__device__ __forceinline__ u64 fmul2(u64 a, u64 b) {
    u64 d; asm("mul.rn.f32x2 %0, %1, %2;" : "=l"(d) : "l"(a), "l"(b)); return d;
}
__device__ __forceinline__ u64 fadd2(u64 a, u64 b) {
    u64 d; asm("add.rn.f32x2 %0, %1, %2;" : "=l"(d) : "l"(a), "l"(b)); return d;
}
__device__ __forceinline__ u64 pack2(float lo, float hi) {
    u64 d; asm("mov.b64 %0, {%1, %2};" : "=l"(d) : "f"(lo), "f"(hi)); return d;
}
__device__ __forceinline__ void unpack2(u64 a, float& lo, float& hi) {
    asm("mov.b64 {%0, %1}, %2;" : "=f"(lo), "=f"(hi) : "l"(a));
}

// ---------------- Kernel 1: per-chunk signature scan (R10 verbatim) --------
__global__ __launch_bounds__(512, 1)
void sig_scan_kernel(const float* __restrict__ path) {
    __shared__ __align__(16) float dxs[CHUNK0 * 12];

    const int b = blockIdx.x >> 1;
    const int c = blockIdx.x & 1;
    const int start = c ? CHUNK0 : 0;
    const int n = c ? (SIG_NSTEP - CHUNK0) : CHUNK0;   // 255 : 256
    const int tid = threadIdx.x;
    const float* prow = path + (size_t)b * SIG_L * SIG_C + (size_t)start * SIG_C;

    for (int i = tid; i < n * SIG_C; i += 512) {
        int t = i / SIG_C;
        int cc = i - t * SIG_C;
        dxs[t * 12 + cc] = prow[(t + 1) * SIG_C + cc] - prow[t * SIG_C + cc];
    }
    __syncthreads();

    if (tid >= 500) return;
    const int i1 = tid / 100;
    const int i2 = (tid / 10) % 10;
    const int i3 = tid % 10;

    const u64 c1_2  = pack2(0.5f, 0.5f);
    const u64 c1_6  = pack2(1.0f / 6.0f, 1.0f / 6.0f);
    const u64 c1_24 = pack2(1.0f / 24.0f, 1.0f / 24.0f);

    u64 l1v2, l2v2, l3_2;
    u64 l4lo[5], l4hi[5];
    {
        float Bv = dxs[i2], Cv = dxs[i3];
        u64 A2 = pack2(dxs[i1], dxs[i1 + 5]);
        float d23 = Bv * Cv;
        u64 d23_2 = pack2(d23, d23);
        u64 B2 = pack2(Bv, Bv);
        l1v2 = A2;
        l2v2 = fmul2(fmul2(A2, B2), c1_2);
        l3_2 = fmul2(fmul2(A2, d23_2), c1_6);
        u64 c4 = fmul2(l3_2, pack2(0.25f, 0.25f));
        float clo, chi; unpack2(c4, clo, chi);
        u64 clo2 = pack2(clo, clo), chi2 = pack2(chi, chi);
        ulonglong2 va = *reinterpret_cast<const ulonglong2*>(dxs);
        ulonglong2 vb = *reinterpret_cast<const ulonglong2*>(dxs + 4);
        u64 vc = *reinterpret_cast<const u64*>(dxs + 8);
        l4lo[0] = fmul2(clo2, va.x); l4hi[0] = fmul2(chi2, va.x);
        l4lo[1] = fmul2(clo2, va.y); l4hi[1] = fmul2(chi2, va.y);
        l4lo[2] = fmul2(clo2, vb.x); l4hi[2] = fmul2(chi2, vb.x);
        l4lo[3] = fmul2(clo2, vb.y); l4hi[3] = fmul2(chi2, vb.y);
        l4lo[4] = fmul2(clo2, vc);   l4hi[4] = fmul2(chi2, vc);
    }

    const float* q1 = dxs + i1 + 12;
    const float* q2 = dxs + i2 + 12;
    const float* q3 = dxs + i3 + 12;
    const char*  qv = reinterpret_cast<const char*>(dxs) + 48;

#pragma unroll 4
    for (int t = 1; t < n; ++t) {
        float A_lo = *q1;
        float A_hi = q1[5];
        float Bv = *q2;
        float Cv = *q3;
        ulonglong2 va = *reinterpret_cast<const ulonglong2*>(qv);
        ulonglong2 vb = *reinterpret_cast<const ulonglong2*>(qv + 16);
        u64 vc = *reinterpret_cast<const u64*>(qv + 32);
        q1 += 12; q2 += 12; q3 += 12; qv += 48;

        float d23 = Bv * Cv;
        u64 A2 = pack2(A_lo, A_hi);
        u64 d23_2 = pack2(d23, d23);
        u64 C2 = pack2(Cv, Cv);
        u64 B2 = pack2(Bv, Bv);
        u64 t1 = fmul2(A2, d23_2);
        u64 uu = fmul2(l2v2, C2);
        u64 vv = fmul2(l1v2, d23_2);
        u64 coef = ffma2(c1_24, t1, ffma2(c1_2, uu, ffma2(c1_6, vv, l3_2)));
        l3_2 = ffma2(c1_6, t1, ffma2(c1_2, vv, fadd2(l3_2, uu)));
        l2v2 = ffma2(ffma2(c1_2, A2, l1v2), B2, l2v2);
        l1v2 = fadd2(l1v2, A2);

        float clo, chi; unpack2(coef, clo, chi);
        u64 clo2 = pack2(clo, clo), chi2 = pack2(chi, chi);
        l4lo[0] = ffma2(clo2, va.x, l4lo[0]); l4hi[0] = ffma2(chi2, va.x, l4hi[0]);
        l4lo[1] = ffma2(clo2, va.y, l4lo[1]); l4hi[1] = ffma2(chi2, va.y, l4hi[1]);
        l4lo[2] = ffma2(clo2, vb.x, l4lo[2]); l4hi[2] = ffma2(chi2, vb.x, l4hi[2]);
        l4lo[3] = ffma2(clo2, vb.y, l4lo[3]); l4hi[3] = ffma2(chi2, vb.y, l4hi[3]);
        l4lo[4] = ffma2(clo2, vc,   l4lo[4]); l4hi[4] = ffma2(chi2, vc,   l4hi[4]);
    }

    float* dst = g_part + ((size_t)b * 2 + c) * SIG_OUT;
    float lo, hi;
    if (i2 == 0 && i3 == 0) {
        unpack2(l1v2, lo, hi);
        dst[i1] = lo; dst[i1 + 5] = hi;
    }
    if (i3 == 0) {
        unpack2(l2v2, lo, hi);
        dst[10 + i1 * 10 + i2] = lo;
        dst[10 + (i1 + 5) * 10 + i2] = hi;
    }
    unpack2(l3_2, lo, hi);
    dst[110 + tid] = lo;
    dst[110 + tid + 500] = hi;
    u64* d4 = reinterpret_cast<u64*>(dst + 1110);
#pragma unroll
    for (int j = 0; j < 5; ++j) {
        d4[j * 1000 + tid]       = l4lo[j];
        d4[j * 1000 + tid + 500] = l4hi[j];
    }
}

// ---------------- Kernel 2: Chen combine, 2 CTAs per batch -----------------
// stage layout (floats): [0,110) head (h=0 only), [110,610) L3 slice,
//                        [610,5610) L4 slice (500 rows x 10)
__global__ __launch_bounds__(512, 1)
void sig_combine_kernel(float* __restrict__ out) {
    __shared__ __align__(16) float As1[10], As2[100];
    __shared__ __align__(16) float Bs1d[16];
    __shared__ __align__(16) float Bs2[100];
    __shared__ __align__(16) float Bs3[1000];
    __shared__ __align__(16) float stage[5610];

    const int b = blockIdx.x >> 1;
    const int h = blockIdx.x & 1;          // p-half
    const int tid = threadIdx.x;
    const float* a  = g_part + (size_t)(2 * b) * SIG_OUT;
    const float* bb = g_part + (size_t)(2 * b + 1) * SIG_OUT;

    for (int i = tid; i < 1000; i += 512) Bs3[i] = bb[110 + i];
    if (tid < 100) { As2[tid] = a[10 + tid]; Bs2[tid] = bb[10 + tid]; }
    if (tid < 16) Bs1d[tid] = (tid < 10) ? bb[tid] : 0.0f;
    if (tid >= 16 && tid < 26) As1[tid - 16] = a[tid - 16];
    __syncthreads();

    if (tid < 500) {
        const int p = h * 500 + tid;
        const int i1 = p / 100;
        const int i2 = (p / 10) % 10;
        const int i3 = p % 10;

        // coalesced u64 loads, issued up front (MLP 10)
        const u64* A4 = reinterpret_cast<const u64*>(a + 1110);
        const u64* B4 = reinterpret_cast<const u64*>(bb + 1110);
        u64 a4[5], b4[5];
#pragma unroll
        for (int j = 0; j < 5; ++j) a4[j] = A4[j * 1000 + p];
#pragma unroll
        for (int j = 0; j < 5; ++j) b4[j] = B4[j * 1000 + p];
        float a3 = a[110 + p];

        float a1 = As1[i1];
        float a2 = As2[i1 * 10 + i2];

        // level 3
        stage[110 + tid] = a3 + Bs3[p] + a2 * Bs1d[i3] + a1 * Bs2[i2 * 10 + i3];

        // level 4
        const u64* B1q = reinterpret_cast<const u64*>(Bs1d);
        const u64* B2q = reinterpret_cast<const u64*>(Bs2 + i3 * 10);
        const u64* B3q = reinterpret_cast<const u64*>(Bs3 + i2 * 100 + i3 * 10);
        u64 a1_2 = pack2(a1, a1);
        u64 a2_2 = pack2(a2, a2);
        u64 a3_2 = pack2(a3, a3);
        u64* s4 = reinterpret_cast<u64*>(stage + 610) + (size_t)tid * 5;
#pragma unroll
        for (int j = 0; j < 5; ++j) {
            u64 s = fadd2(a4[j], b4[j]);
            s = ffma2(a3_2, B1q[j], s);
            s = ffma2(a2_2, B2q[j], s);
            s = ffma2(a1_2, B3q[j], s);
            s4[j] = s;
        }
    }

    // head (levels 1+2) by threads 0..109 of h=0 (they double-duty; no smem
    // write overlap with the row work above, which writes stage[110,5610)).
    if (h == 0 && tid < 110) {
        if (tid < 10) {
            stage[tid] = As1[tid] + Bs1d[tid];
        } else {
            int m = tid - 10;
            stage[tid] = As2[m] + Bs2[m] + As1[m / 10] * Bs1d[m % 10];
        }
    }
    __syncthreads();

    // coalesced u64 copies: stage -> out
    float* ob = out + (size_t)b * SIG_OUT;
    if (h == 0) {
        // head + lower L3 are contiguous in out: [0,610)
        const u64* sp = reinterpret_cast<const u64*>(stage);
        u64* op = reinterpret_cast<u64*>(ob);
        for (int i = tid; i < 305; i += 512) op[i] = sp[i];
        const u64* sp4 = reinterpret_cast<const u64*>(stage + 610);
        u64* op4 = reinterpret_cast<u64*>(ob + 1110);
        for (int i = tid; i < 2500; i += 512) op4[i] = sp4[i];
    } else {
        const u64* sp = reinterpret_cast<const u64*>(stage + 110);
        u64* op = reinterpret_cast<u64*>(ob + 610);
        for (int i = tid; i < 250; i += 512) op[i] = sp[i];
        const u64* sp4 = reinterpret_cast<const u64*>(stage + 610);
        u64* op4 = reinterpret_cast<u64*>(ob + 6110);
        for (int i = tid; i < 2500; i += 512) op4[i] = sp4[i];
    }
}

extern "C" void kernel_launch(void* const* d_in, const int* in_sizes, int n_in,
                              void* d_out, int out_size) {
    const float* path = (const float*)d_in[0];
    float* out = (float*)d_out;
    int B = in_sizes[0] / (SIG_L * SIG_C);
    if (B > SIG_MAXB) B = SIG_MAXB;
    sig_scan_kernel<<<B * 2, 512>>>(path);
    sig_combine_kernel<<<B * 2, 512>>>(out);
}